// round 16
// baseline (speedup 1.0000x reference)
#include <cuda_runtime.h>
#include <cuda_bf16.h>
#include <math.h>

#define BATCH    4
#define SEQ      1024
#define M_ROWS   4096
#define D_MODEL  256
#define D_INNER  512
#define D_STATE  16
#define DT_RANK  16
#define D_CONV   4
#define N_LAYERS 2
#define X_DIM    768
#define N_CLS    128

#define NCHUNK   16
#define CHUNK    64
#define NGROUP   (BATCH * D_INNER)

typedef unsigned int u32;
typedef unsigned short u16;

// ---------------------------------------------------------------------------
// Scratch (fp32)
// ---------------------------------------------------------------------------
__device__ float g_hl  [M_ROWS * D_MODEL];
__device__ float g_xz  [M_ROWS * 2 * D_INNER];
__device__ float g_u   [M_ROWS * D_INNER];
__device__ float g_ut  [M_ROWS * D_INNER];
__device__ float g_dltt[M_ROWS * D_INNER];
__device__ float g_yt  [M_ROWS * D_INNER];
__device__ float g_xdbc[M_ROWS * 48];
__device__ float g_norm[M_ROWS];
__device__ float g_part[4 * M_ROWS * D_MODEL];

// bf16 hi/lo operand buffers
__device__ __nv_bfloat16 g_lthi[M_ROWS * D_MODEL], g_ltlo[M_ROWS * D_MODEL];
__device__ __nv_bfloat16 g_yhi [M_ROWS * D_INNER], g_ylo [M_ROWS * D_INNER];
__device__ __nv_bfloat16 g_hshi[M_ROWS * D_MODEL], g_hslo[M_ROWS * D_MODEL];
__device__ __nv_bfloat16 g_h2hi[M_ROWS * D_MODEL], g_h2lo[M_ROWS * D_MODEL];
__device__ __nv_bfloat16 g_wihi[D_MODEL * X_DIM],  g_wilo[D_MODEL * X_DIM];
__device__ __nv_bfloat16 g_wphi[N_LAYERS * 2 * D_INNER * D_MODEL], g_wplo[N_LAYERS * 2 * D_INNER * D_MODEL];
__device__ __nv_bfloat16 g_wohi[N_LAYERS * D_MODEL * D_INNER],     g_wolo[N_LAYERS * D_MODEL * D_INNER];
__device__ __nv_bfloat16 g_wqhi[D_MODEL * D_MODEL], g_wqlo[D_MODEL * D_MODEL];
__device__ __nv_bfloat16 g_wchi[N_CLS * D_MODEL],   g_wclo[N_CLS * D_MODEL];

__device__ __forceinline__ float gelu_f(float v) {
    return 0.5f * v * (1.f + erff(v * 0.70710678118654752f));
}
__device__ __forceinline__ float silu_f(float v) {
    return v / (1.f + __expf(-v));
}
__device__ __forceinline__ u32 s2u(const void* p) {
    u32 a;
    asm("{ .reg .u64 t; cvta.to.shared.u64 t, %1; cvt.u32.u64 %0, t; }" : "=r"(a) : "l"(p));
    return a;
}

// ---------------------------------------------------------------------------
// Warp-MMA primitives
// ---------------------------------------------------------------------------
#define LDSM4(r, addr) \
    asm volatile("ldmatrix.sync.aligned.m8n8.x4.shared.b16 {%0,%1,%2,%3}, [%4];" \
        : "=r"((r)[0]), "=r"((r)[1]), "=r"((r)[2]), "=r"((r)[3]) : "r"(addr))

#define MMA16816(c, a, b0, b1) \
    asm volatile("mma.sync.aligned.m16n8k16.row.col.f32.bf16.bf16.f32 " \
        "{%0,%1,%2,%3}, {%4,%5,%6,%7}, {%8,%9}, {%0,%1,%2,%3};" \
        : "+f"((c)[0]), "+f"((c)[1]), "+f"((c)[2]), "+f"((c)[3]) \
        : "r"((a)[0]), "r"((a)[1]), "r"((a)[2]), "r"((a)[3]), "r"(b0), "r"(b1))

#define CPA(s, g)  asm volatile("cp.async.cg.shared.global [%0], [%1], 16;" :: "r"(s), "l"(g))
#define CPC()      asm volatile("cp.async.commit_group;" ::: "memory")
#define CPW0()     asm volatile("cp.async.wait_group 0;" ::: "memory")
#define CPW1()     asm volatile("cp.async.wait_group 1;" ::: "memory")

// smem: A tensors 128 rows x 64B (8KB each), B tensors 64 rows x 64B (4KB each)
// layout per buffer: [Ahi 8K][Alo 8K][Bhi 4K][Blo 4K] = 24KB; 2 buffers = 48KB.
// XOR swizzle on 16B units: x = u ^ ((row>>1)&3) -> conflict-free.
#define ABYTES 8192
#define BBYTES 4096
#define BUFB   (2 * ABYTES + 2 * BBYTES)      // 24576
#define MM_SMEM (2 * BUFB)                    // 49152
#define SWZ_OFF(row, u) ((u32)((row) * 64 + ((((u) ^ (((row) >> 1) & 3)) & 3) << 4)))

// fp32 -> (bf16 hi, bf16 lo)
__device__ __forceinline__ void bf16_hilo4(const float4& v,
                                           __nv_bfloat16* hi, __nv_bfloat16* lo)
{
    __nv_bfloat16 h0 = __float2bfloat16(v.x), h1 = __float2bfloat16(v.y);
    __nv_bfloat16 h2 = __float2bfloat16(v.z), h3 = __float2bfloat16(v.w);
    hi[0] = h0; hi[1] = h1; hi[2] = h2; hi[3] = h3;
    lo[0] = __float2bfloat16(v.x - __bfloat162float(h0));
    lo[1] = __float2bfloat16(v.y - __bfloat162float(h1));
    lo[2] = __float2bfloat16(v.z - __bfloat162float(h2));
    lo[3] = __float2bfloat16(v.w - __bfloat162float(h3));
}

// ---------------------------------------------------------------------------
// Split-bf16 tensor-core GEMM (hi*hi + hi*lo + lo*hi).
// 128x64 CTA tile, 8 warps of 32x32, BK=32, cp.async double-buffered.
// CVTA=1: Ahi is const float* (fp32 A converted on the fly; Alo ignored).
// Requires M%128==0, N%64==0, (K/SPLIT)%32==0.
// ---------------------------------------------------------------------------
template<int SPLIT, int CVTA>
__global__ __launch_bounds__(256) void mma_gemm(
    const __nv_bfloat16* __restrict__ Ahi, const __nv_bfloat16* __restrict__ Alo,
    const __nv_bfloat16* __restrict__ Bhi, const __nv_bfloat16* __restrict__ Blo,
    float* __restrict__ C, int M, int N, int K)
{
    extern __shared__ u16 sm[];
    const int tid  = threadIdx.x;
    const int wid  = tid >> 5;
    const int lane = tid & 31;
    const int m0 = blockIdx.y * 128, n0 = blockIdx.x * 64;
    const int Kc = K / SPLIT;
    const int kbeg = blockIdx.z * Kc;
    const u32 sbase = s2u(sm);
    char* smc = (char*)sm;

    const float* Af = (const float*)Ahi;
    const __nv_bfloat16* gpA[2] = {Ahi + (size_t)m0 * K + kbeg, Alo + (size_t)m0 * K + kbeg};
    const __nv_bfloat16* gpB[2] = {Bhi + (size_t)n0 * K + kbeg, Blo + (size_t)n0 * K + kbeg};

    const int wm0 = (wid & 3) * 32;   // 0,32,64,96
    const int wn0 = (wid >> 2) * 32;  // 0,32

    float acc[2][4][4];
    #pragma unroll
    for (int i = 0; i < 2; i++)
        #pragma unroll
        for (int j = 0; j < 4; j++)
            #pragma unroll
            for (int q = 0; q < 4; q++) acc[i][j][q] = 0.f;

    const int nch = Kc / 32;

    // ---- prologue: chunk 0 -> buf 0 ----
    if (CVTA) {
        // A: fp32 LDG -> hi/lo STS (512 row-units / 256 thr = 2 per thread)
        #pragma unroll
        for (int i = 0; i < 2; i++) {
            int idx = tid + i * 256;
            int row = idx >> 2, u = idx & 3;
            const float* src = Af + (size_t)(m0 + row) * K + kbeg + u * 8;
            float4 v0 = *(const float4*)src;
            float4 v1 = *(const float4*)(src + 4);
            __align__(16) __nv_bfloat16 hi[8], lo[8];
            bf16_hilo4(v0, hi, lo); bf16_hilo4(v1, hi + 4, lo + 4);
            u32 off = SWZ_OFF(row, u);
            *(uint4*)(smc + off) = *(uint4*)hi;
            *(uint4*)(smc + ABYTES + off) = *(uint4*)lo;
        }
        // B: 512 units / 256 thr = 2 per thread
        #pragma unroll
        for (int i = 0; i < 2; i++) {
            int idx = tid + i * 256;
            int tno = idx >> 8, unit = idx & 255;
            int row = unit >> 2, u = unit & 3;
            u32 s = sbase + (u32)(2 * ABYTES + tno * BBYTES) + SWZ_OFF(row, u);
            CPA(s, (const void*)(gpB[tno] + (size_t)row * K + u * 8));
        }
    } else {
        // A: 1024 units, B: 512 units -> 6 per thread
        #pragma unroll
        for (int i = 0; i < 6; i++) {
            int idx = tid + i * 256;
            if (idx < 1024) {
                int tno = idx >> 9, unit = idx & 511;
                int row = unit >> 2, u = unit & 3;
                u32 s = sbase + (u32)(tno * ABYTES) + SWZ_OFF(row, u);
                CPA(s, (const void*)(gpA[tno] + (size_t)row * K + u * 8));
            } else {
                int j = idx - 1024;
                int tno = j >> 8, unit = j & 255;
                int row = unit >> 2, u = unit & 3;
                u32 s = sbase + (u32)(2 * ABYTES + tno * BBYTES) + SWZ_OFF(row, u);
                CPA(s, (const void*)(gpB[tno] + (size_t)row * K + u * 8));
            }
        }
    }
    CPC();

    for (int c = 0; c < nch; c++) {
        const int b = c & 1;
        float4 av[4];
        if (c + 1 < nch) {
            const int k0 = (c + 1) * 32;
            const u32 bb = (u32)((b ^ 1) * BUFB);
            if (CVTA) {
                #pragma unroll
                for (int i = 0; i < 2; i++) {
                    int idx = tid + i * 256;
                    int row = idx >> 2, u = idx & 3;
                    const float* src = Af + (size_t)(m0 + row) * K + kbeg + k0 + u * 8;
                    av[i * 2 + 0] = *(const float4*)src;
                    av[i * 2 + 1] = *(const float4*)(src + 4);
                }
                #pragma unroll
                for (int i = 0; i < 2; i++) {
                    int idx = tid + i * 256;
                    int tno = idx >> 8, unit = idx & 255;
                    int row = unit >> 2, u = unit & 3;
                    u32 s = sbase + bb + (u32)(2 * ABYTES + tno * BBYTES) + SWZ_OFF(row, u);
                    CPA(s, (const void*)(gpB[tno] + (size_t)row * K + k0 + u * 8));
                }
            } else {
                #pragma unroll
                for (int i = 0; i < 6; i++) {
                    int idx = tid + i * 256;
                    if (idx < 1024) {
                        int tno = idx >> 9, unit = idx & 511;
                        int row = unit >> 2, u = unit & 3;
                        u32 s = sbase + bb + (u32)(tno * ABYTES) + SWZ_OFF(row, u);
                        CPA(s, (const void*)(gpA[tno] + (size_t)row * K + k0 + u * 8));
                    } else {
                        int j = idx - 1024;
                        int tno = j >> 8, unit = j & 255;
                        int row = unit >> 2, u = unit & 3;
                        u32 s = sbase + bb + (u32)(2 * ABYTES + tno * BBYTES) + SWZ_OFF(row, u);
                        CPA(s, (const void*)(gpB[tno] + (size_t)row * K + k0 + u * 8));
                    }
                }
            }
            CPC();
            CPW1();
        } else {
            CPW0();
        }
        __syncthreads();

        const u32 base = sbase + (u32)(b * BUFB);
        #pragma unroll
        for (int kk = 0; kk < 32; kk += 16) {
            const int id = lane >> 3;
            u32 ah[2][4], al[2][4];
            #pragma unroll
            for (int mt = 0; mt < 2; mt++) {
                int lrow = wm0 + mt * 16 + ((id & 1) << 3) + (lane & 7);
                int au = (kk >> 3) + (id >> 1);
                u32 off = SWZ_OFF(lrow, au);
                LDSM4(ah[mt], base + off);
                LDSM4(al[mt], base + (u32)ABYTES + off);
            }
            u32 bh[2][4], bl[2][4];
            #pragma unroll
            for (int p = 0; p < 2; p++) {
                int brow = wn0 + (2 * p + (id >> 1)) * 8 + (lane & 7);
                int bu = (kk >> 3) + (id & 1);
                u32 off = SWZ_OFF(brow, bu);
                LDSM4(bh[p], base + (u32)(2 * ABYTES) + off);
                LDSM4(bl[p], base + (u32)(2 * ABYTES + BBYTES) + off);
            }
            #pragma unroll
            for (int mt = 0; mt < 2; mt++)
                #pragma unroll
                for (int nt = 0; nt < 4; nt++) {
                    const int p = nt >> 1, o = (nt & 1) * 2;
                    MMA16816(acc[mt][nt], ah[mt], bh[p][o], bh[p][o + 1]);
                    MMA16816(acc[mt][nt], ah[mt], bl[p][o], bl[p][o + 1]);
                    MMA16816(acc[mt][nt], al[mt], bh[p][o], bh[p][o + 1]);
                }
        }
        if (CVTA && c + 1 < nch) {
            char* bb = smc + (b ^ 1) * BUFB;
            #pragma unroll
            for (int i = 0; i < 2; i++) {
                int idx = tid + i * 256;
                int row = idx >> 2, u = idx & 3;
                __align__(16) __nv_bfloat16 hi[8], lo[8];
                bf16_hilo4(av[i * 2 + 0], hi, lo);
                bf16_hilo4(av[i * 2 + 1], hi + 4, lo + 4);
                u32 off = SWZ_OFF(row, u);
                *(uint4*)(bb + off) = *(uint4*)hi;
                *(uint4*)(bb + ABYTES + off) = *(uint4*)lo;
            }
        }
        __syncthreads();
    }

    float* Cout = (SPLIT > 1) ? (C + (size_t)blockIdx.z * M * N) : C;
    #pragma unroll
    for (int mt = 0; mt < 2; mt++) {
        const int row = m0 + wm0 + mt * 16 + (lane >> 2);
        #pragma unroll
        for (int nt = 0; nt < 4; nt++) {
            const int col = n0 + wn0 + nt * 8 + (lane & 3) * 2;
            *(float2*)(Cout + (size_t)row * N + col) =
                make_float2(acc[mt][nt][0], acc[mt][nt][1]);
            *(float2*)(Cout + (size_t)(row + 8) * N + col) =
                make_float2(acc[mt][nt][2], acc[mt][nt][3]);
        }
    }
}

// ---------------------------------------------------------------------------
// Batched weight conversion: 5 tensors, 1 launch.
// ---------------------------------------------------------------------------
#define CV_N1 (D_MODEL * X_DIM)
#define CV_N2 (N_LAYERS * 2 * D_INNER * D_MODEL)
#define CV_N3 (N_LAYERS * D_MODEL * D_INNER)
#define CV_N4 (D_MODEL * D_MODEL)
#define CV_N5 (N_CLS * D_MODEL)
#define CV_TOT (CV_N1 + CV_N2 + CV_N3 + CV_N4 + CV_N5)

__global__ void cvt_all(const float* __restrict__ s1,
                        const float* __restrict__ s2, const float* __restrict__ s3,
                        const float* __restrict__ s4, const float* __restrict__ s5,
                        __nv_bfloat16* h1, __nv_bfloat16* l1,
                        __nv_bfloat16* h2, __nv_bfloat16* l2,
                        __nv_bfloat16* h3, __nv_bfloat16* l3,
                        __nv_bfloat16* h4, __nv_bfloat16* l4,
                        __nv_bfloat16* h5, __nv_bfloat16* l5)
{
    int gi = (blockIdx.x * blockDim.x + threadIdx.x) * 4;
    const int stride = gridDim.x * blockDim.x * 4;
    for (; gi < CV_TOT; gi += stride) {
        const float* src; __nv_bfloat16 *hi, *lo; int off = gi;
        if (off < CV_N1) { src = s1; hi = h1; lo = l1; }
        else if ((off -= CV_N1) < CV_N2) { src = s2; hi = h2; lo = l2; }
        else if ((off -= CV_N2) < CV_N3) { src = s3; hi = h3; lo = l3; }
        else if ((off -= CV_N3) < CV_N4) { src = s4; hi = h4; lo = l4; }
        else { off -= CV_N4; src = s5; hi = h5; lo = l5; }
        float4 v = *(const float4*)(src + off);
        bf16_hilo4(v, hi + off, lo + off);
    }
}

// ---------------------------------------------------------------------------
// xpw GEMM (N=48) FFMA split-K
// ---------------------------------------------------------------------------
__global__ __launch_bounds__(256) void gemm_xpw(
    const float* __restrict__ A, const float* __restrict__ W,
    float* __restrict__ Cp, int M, int N, int K, int splitK)
{
    __shared__ float As[16][132];
    __shared__ float Ws[16][68];
    const int tid = threadIdx.x;
    const int m0 = blockIdx.y * 128;
    const int Kc = K / splitK;
    const int kbeg = blockIdx.z * Kc;
    const int tm = tid >> 4;
    const int tn = tid & 15;
    const int lr = tid >> 2;
    const int lc = (tid & 3) * 4;

    float acc[8][4] = {};

    for (int k0 = kbeg; k0 < kbeg + Kc; k0 += 16) {
        #pragma unroll
        for (int i = 0; i < 2; i++) {
            int r = lr + i * 64;
            float4 v = *(const float4*)(A + (size_t)(m0 + r) * K + k0 + lc);
            As[lc + 0][r] = v.x; As[lc + 1][r] = v.y;
            As[lc + 2][r] = v.z; As[lc + 3][r] = v.w;
        }
        {
            float4 v = make_float4(0.f, 0.f, 0.f, 0.f);
            if (lr < N)
                v = *(const float4*)(W + (size_t)lr * K + k0 + lc);
            Ws[lc + 0][lr] = v.x; Ws[lc + 1][lr] = v.y;
            Ws[lc + 2][lr] = v.z; Ws[lc + 3][lr] = v.w;
        }
        __syncthreads();
        #pragma unroll
        for (int kk = 0; kk < 16; kk++) {
            float a[8], b[4];
            *(float4*)&a[0] = *(const float4*)&As[kk][tm * 8];
            *(float4*)&a[4] = *(const float4*)&As[kk][tm * 8 + 4];
            *(float4*)&b[0] = *(const float4*)&Ws[kk][tn * 4];
            #pragma unroll
            for (int i = 0; i < 8; i++)
                #pragma unroll
                for (int j = 0; j < 4; j++)
                    acc[i][j] = fmaf(a[i], b[j], acc[i][j]);
        }
        __syncthreads();
    }

    const int n = tn * 4;
    if (n >= N) return;
    float* Cout = Cp + (size_t)blockIdx.z * M * N;
    #pragma unroll
    for (int i = 0; i < 8; i++) {
        int m = m0 + tm * 8 + i;
        float4 v = {acc[i][0], acc[i][1], acc[i][2], acc[i][3]};
        *(float4*)(Cout + (size_t)m * N + n) = v;
    }
}

template<int S, int BIAS>
__global__ void reduce_k(const float* __restrict__ part, const float* __restrict__ bias,
                         float* __restrict__ out, int MN, int N)
{
    int i4 = (blockIdx.x * blockDim.x + threadIdx.x) * 4;
    if (i4 >= MN) return;
    float4 v = *(const float4*)(part + i4);
    #pragma unroll
    for (int s = 1; s < S; s++) {
        float4 p = *(const float4*)(part + (size_t)s * MN + i4);
        v.x += p.x; v.y += p.y; v.z += p.z; v.w += p.w;
    }
    if (BIAS) {
        float4 bv = *(const float4*)(bias + (i4 % N));
        v.x += bv.x; v.y += bv.y; v.z += bv.z; v.w += bv.w;
    }
    *(float4*)(out + i4) = v;
}

// ---------------------------------------------------------------------------
// Warp-per-row epilogues
// ---------------------------------------------------------------------------
__device__ __forceinline__ void warp_stats(const float4& v0, const float4& v1,
                                           float& mu, float& rstd)
{
    float s1 = v0.x + v0.y + v0.z + v0.w + v1.x + v1.y + v1.z + v1.w;
    float s2 = v0.x*v0.x + v0.y*v0.y + v0.z*v0.z + v0.w*v0.w
             + v1.x*v1.x + v1.y*v1.y + v1.z*v1.z + v1.w*v1.w;
    #pragma unroll
    for (int o = 16; o > 0; o >>= 1) {
        s1 += __shfl_xor_sync(0xffffffffu, s1, o);
        s2 += __shfl_xor_sync(0xffffffffu, s2, o);
    }
    mu = s1 * (1.f / 256.f);
    rstd = rsqrtf(s2 * (1.f / 256.f) - mu * mu + 1e-5f);
}
__device__ __forceinline__ float4 ln_apply4(const float4& v, float mu, float rstd,
                                            const float4& g, const float4& b)
{
    float4 o;
    o.x = (v.x - mu) * rstd * g.x + b.x;
    o.y = (v.y - mu) * rstd * g.y + b.y;
    o.z = (v.z - mu) * rstd * g.z + b.z;
    o.w = (v.w - mu) * rstd * g.w + b.w;
    return o;
}
__device__ __forceinline__ float4 gelu4(float4 v) {
    v.x = gelu_f(v.x); v.y = gelu_f(v.y); v.z = gelu_f(v.z); v.w = gelu_f(v.w);
    return v;
}
__device__ __forceinline__ void add4(float4& a, const float4& b) {
    a.x += b.x; a.y += b.y; a.z += b.z; a.w += b.w;
}

template<int S>
__global__ void ep_inproj(const float* __restrict__ part, const float* __restrict__ bias,
                          const float* __restrict__ lng, const float* __restrict__ lnb,
                          const float* __restrict__ ng0, const float* __restrict__ nb0,
                          float* __restrict__ hs,
                          __nv_bfloat16* __restrict__ lthi, __nv_bfloat16* __restrict__ ltlo)
{
    const int gi = blockIdx.x * blockDim.x + threadIdx.x;
    const int row = gi >> 5;
    const int lane = gi & 31;
    const int MN = M_ROWS * D_MODEL;
    const int c0 = lane * 4, c1 = 128 + lane * 4;
    const size_t i0 = (size_t)row * D_MODEL + c0;
    const size_t i1 = (size_t)row * D_MODEL + c1;
    float4 v0 = *(const float4*)(part + i0);
    float4 v1 = *(const float4*)(part + i1);
    #pragma unroll
    for (int s = 1; s < S; s++) {
        add4(v0, *(const float4*)(part + (size_t)s * MN + i0));
        add4(v1, *(const float4*)(part + (size_t)s * MN + i1));
    }
    add4(v0, *(const float4*)(bias + c0));
    add4(v1, *(const float4*)(bias + c1));
    float mu, rstd;
    warp_stats(v0, v1, mu, rstd);
    float4 g0 = *(const float4*)(lng + c0), g1 = *(const float4*)(lng + c1);
    float4 bb0 = *(const float4*)(lnb + c0), bb1 = *(const float4*)(lnb + c1);
    float4 w0 = gelu4(ln_apply4(v0, mu, rstd, g0, bb0));
    float4 w1 = gelu4(ln_apply4(v1, mu, rstd, g1, bb1));
    *(float4*)(hs + i0) = w0;
    *(float4*)(hs + i1) = w1;
    warp_stats(w0, w1, mu, rstd);
    g0 = *(const float4*)(ng0 + c0); g1 = *(const float4*)(ng0 + c1);
    bb0 = *(const float4*)(nb0 + c0); bb1 = *(const float4*)(nb0 + c1);
    float4 t0 = ln_apply4(w0, mu, rstd, g0, bb0);
    float4 t1 = ln_apply4(w1, mu, rstd, g1, bb1);
    bf16_hilo4(t0, lthi + i0, ltlo + i0);
    bf16_hilo4(t1, lthi + i1, ltlo + i1);
}

template<int S, int LN>
__global__ void ep_opw(const float* __restrict__ part, const float* __restrict__ ng,
                       const float* __restrict__ nb, float* __restrict__ hs,
                       __nv_bfloat16* __restrict__ ohi, __nv_bfloat16* __restrict__ olo)
{
    const int gi = blockIdx.x * blockDim.x + threadIdx.x;
    const int row = gi >> 5;
    const int lane = gi & 31;
    const int MN = M_ROWS * D_MODEL;
    const int c0 = lane * 4, c1 = 128 + lane * 4;
    const size_t i0 = (size_t)row * D_MODEL + c0;
    const size_t i1 = (size_t)row * D_MODEL + c1;
    float4 v0 = *(const float4*)(hs + i0);
    float4 v1 = *(const float4*)(hs + i1);
    #pragma unroll
    for (int s = 0; s < S; s++) {
        add4(v0, *(const float4*)(part + (size_t)s * MN + i0));
        add4(v1, *(const float4*)(part + (size_t)s * MN + i1));
    }
    *(float4*)(hs + i0) = v0;
    *(float4*)(hs + i1) = v1;
    if (LN) {
        float mu, rstd;
        warp_stats(v0, v1, mu, rstd);
        float4 g0 = *(const float4*)(ng + c0), g1 = *(const float4*)(ng + c1);
        float4 b0 = *(const float4*)(nb + c0), b1 = *(const float4*)(nb + c1);
        float4 t0 = ln_apply4(v0, mu, rstd, g0, b0);
        float4 t1 = ln_apply4(v1, mu, rstd, g1, b1);
        bf16_hilo4(t0, ohi + i0, olo + i0);
        bf16_hilo4(t1, ohi + i1, olo + i1);
    } else {
        bf16_hilo4(v0, ohi + i0, olo + i0);
        bf16_hilo4(v1, ohi + i1, olo + i1);
    }
}

template<int S>
__global__ void ep_head(const float* __restrict__ part, const float* __restrict__ bias,
                        __nv_bfloat16* __restrict__ h2hi, __nv_bfloat16* __restrict__ h2lo,
                        float* __restrict__ nrm)
{
    const int gi = blockIdx.x * blockDim.x + threadIdx.x;
    const int row = gi >> 5;
    const int lane = gi & 31;
    const int MN = M_ROWS * D_MODEL;
    const int c0 = lane * 4, c1 = 128 + lane * 4;
    const size_t i0 = (size_t)row * D_MODEL + c0;
    const size_t i1 = (size_t)row * D_MODEL + c1;
    float4 v0 = *(const float4*)(part + i0);
    float4 v1 = *(const float4*)(part + i1);
    #pragma unroll
    for (int s = 1; s < S; s++) {
        add4(v0, *(const float4*)(part + (size_t)s * MN + i0));
        add4(v1, *(const float4*)(part + (size_t)s * MN + i1));
    }
    add4(v0, *(const float4*)(bias + c0));
    add4(v1, *(const float4*)(bias + c1));
    v0 = gelu4(v0); v1 = gelu4(v1);
    bf16_hilo4(v0, h2hi + i0, h2lo + i0);
    bf16_hilo4(v1, h2hi + i1, h2lo + i1);
    float s = v0.x*v0.x + v0.y*v0.y + v0.z*v0.z + v0.w*v0.w
            + v1.x*v1.x + v1.y*v1.y + v1.z*v1.z + v1.w*v1.w;
    #pragma unroll
    for (int o = 16; o > 0; o >>= 1) s += __shfl_xor_sync(0xffffffffu, s, o);
    if (lane == 0) nrm[row] = sqrtf(s);
}

// ---------------------------------------------------------------------------
// Depthwise causal conv (k=4) + SiLU -> u and ut
// ---------------------------------------------------------------------------
__global__ void conv2_kernel(const float* __restrict__ xz, const float* __restrict__ cw,
                             const float* __restrict__ cb, float* __restrict__ u,
                             float* __restrict__ ut)
{
    __shared__ float tile[32][33];
    const int b = blockIdx.z;
    const int t0 = blockIdx.x * 32, d0 = blockIdx.y * 32;
    const int tx = threadIdx.x, ty = threadIdx.y;
    const int d = d0 + tx;
    const float w0 = cw[d * 4 + 0], w1 = cw[d * 4 + 1];
    const float w2 = cw[d * 4 + 2], w3 = cw[d * 4 + 3];
    const float bb = cb[d];
    #pragma unroll
    for (int i = 0; i < 4; i++) {
        const int t = t0 + ty + i * 8;
        const size_t rbase = (size_t)(b * SEQ + t) * (2 * D_INNER) + d;
        float acc = bb;
        if (t >= 3) {
            acc = fmaf(w0, xz[rbase - 3 * 2 * D_INNER], acc);
            acc = fmaf(w1, xz[rbase - 2 * 2 * D_INNER], acc);
            acc = fmaf(w2, xz[rbase - 1 * 2 * D_INNER], acc);
        } else {
            if (t >= 2) acc = fmaf(w1, xz[rbase - 2 * 2 * D_INNER], acc);
            if (t >= 1) acc = fmaf(w2, xz[rbase - 1 * 2 * D_INNER], acc);
        }
        acc = fmaf(w3, xz[rbase], acc);
        acc = silu_f(acc);
        u[(size_t)(b * SEQ + t) * D_INNER + d] = acc;
        tile[ty + i * 8][tx] = acc;
    }
    __syncthreads();
    #pragma unroll
    for (int i = 0; i < 4; i++) {
        const int dd = d0 + ty + i * 8;
        ut[(size_t)(b * D_INNER + dd) * SEQ + t0 + tx] = tile[tx][ty + i * 8];
    }
}

// ---------------------------------------------------------------------------
// delta = softplus(dt @ dtw^T + dtb) -> dltt [b][d][t]
// ---------------------------------------------------------------------------
__global__ void deltaT_kernel(const float* __restrict__ xdbc, const float* __restrict__ dtw,
                              const float* __restrict__ dtb, float* __restrict__ dltt)
{
    __shared__ float w_s[32][17];
    __shared__ float b_s[32];
    __shared__ float tile[32][33];
    const int b = blockIdx.z;
    const int t0 = blockIdx.x * 32, d0 = blockIdx.y * 32;
    const int tx = threadIdx.x, ty = threadIdx.y;
    const int tid = ty * 32 + tx;
    {
        int r = tid >> 4, c = tid & 15;
        w_s[r][c] = dtw[(d0 + r) * DT_RANK + c];
        w_s[r + 16][c] = dtw[(d0 + r + 16) * DT_RANK + c];
        if (tid < 32) b_s[tid] = dtb[d0 + tid];
    }
    __syncthreads();
    #pragma unroll
    for (int i = 0; i < 4; i++) {
        const int t = t0 + ty + i * 8;
        const float* xr = xdbc + (size_t)(b * SEQ + t) * 48;
        float acc = b_s[tx];
        #pragma unroll
        for (int r = 0; r < DT_RANK; r++)
            acc = fmaf(__ldg(xr + r), w_s[tx][r], acc);
        tile[ty + i * 8][tx] = (acc > 20.f) ? acc : log1pf(__expf(acc));
    }
    __syncthreads();
    #pragma unroll
    for (int i = 0; i < 4; i++) {
        const int dd = d0 + ty + i * 8;
        dltt[(size_t)(b * D_INNER + dd) * SEQ + t0 + tx] = tile[tx][ty + i * 8];
    }
}

// ---------------------------------------------------------------------------
// Fused chunked selective scan (small smem, high occupancy)
// ---------------------------------------------------------------------------
__global__ __launch_bounds__(256) void scan_fused(
    const float* __restrict__ dltt, const float* __restrict__ ut,
    const float* __restrict__ xdbc, const float* __restrict__ A_log,
    const float* __restrict__ Dp, float* __restrict__ yt)
{
    __shared__ float Ps[NCHUNK][D_STATE];
    __shared__ float Qs[NCHUNK][D_STATE];
    __shared__ float Ts[NCHUNK][D_STATE];
    const int tid = threadIdx.x;
    const int g = blockIdx.x;
    const int c = tid >> 4;
    const int n = tid & 15;
    const int b = g >> 9;
    const int d = g & (D_INNER - 1);
    const float A  = -__expf(A_log[d * D_STATE + n]);
    const float Dd = Dp[d];
    const size_t base = (size_t)g * SEQ + c * CHUNK;
    const float* xb = xdbc + ((size_t)b * SEQ + c * CHUNK) * 48 + DT_RANK;

    float dt[16], uu[16];
    if (c < NCHUNK - 1) {
        float s = 0.f, sumd = 0.f;
        for (int tc = 0; tc < CHUNK; tc += 16) {
            #pragma unroll
            for (int q = 0; q < 4; q++) {
                float4 v = ((const float4*)(dltt + base + tc))[q];
                dt[q*4+0] = v.x; dt[q*4+1] = v.y; dt[q*4+2] = v.z; dt[q*4+3] = v.w;
                float4 w = ((const float4*)(ut + base + tc))[q];
                uu[q*4+0] = w.x; uu[q*4+1] = w.y; uu[q*4+2] = w.z; uu[q*4+3] = w.w;
            }
            #pragma unroll
            for (int j = 0; j < 16; j++) {
                const float Bn = __ldg(xb + (size_t)(tc + j) * 48 + n);
                s = fmaf(s, __expf(dt[j] * A), dt[j] * uu[j] * Bn);
                sumd += dt[j];
            }
        }
        Qs[c][n] = s;
        Ps[c][n] = __expf(A * sumd);
    }
    __syncthreads();

    if (tid < D_STATE) {
        float t = 0.f;
        Ts[0][tid] = 0.f;
        #pragma unroll
        for (int cc = 1; cc < NCHUNK; cc++) {
            t = fmaf(Ps[cc - 1][tid], t, Qs[cc - 1][tid]);
            Ts[cc][tid] = t;
        }
    }
    __syncthreads();

    {
        float s = Ts[c][n];
        for (int tc = 0; tc < CHUNK; tc += 16) {
            #pragma unroll
            for (int q = 0; q < 4; q++) {
                float4 v = ((const float4*)(dltt + base + tc))[q];
                dt[q*4+0] = v.x; dt[q*4+1] = v.y; dt[q*4+2] = v.z; dt[q*4+3] = v.w;
                float4 w = ((const float4*)(ut + base + tc))[q];
                uu[q*4+0] = w.x; uu[q*4+1] = w.y; uu[q*4+2] = w.z; uu[q*4+3] = w.w;
            }
            float rv = 0.f;
            #pragma unroll
            for (int j = 0; j < 16; j++) {
                const float* xr = xb + (size_t)(tc + j) * 48;
                const float Bn = __ldg(xr + n);
                const float Cn = __ldg(xr + D_STATE + n);
                s = fmaf(s, __expf(dt[j] * A), dt[j] * uu[j] * Bn);
                float v = s * Cn;
                #pragma unroll
                for (int o = 8; o > 0; o >>= 1) v += __shfl_xor_sync(0xffffffffu, v, o);
                if (n == j) rv = v + uu[j] * Dd;
            }
            yt[base + tc + n] = rv;
        }
    }
}

// ---------------------------------------------------------------------------
// Gate + transpose -> y hi/lo
// ---------------------------------------------------------------------------
__global__ void gate_kernel(const float* __restrict__ yt, const float* __restrict__ xz,
                            __nv_bfloat16* __restrict__ yhi, __nv_bfloat16* __restrict__ ylo)
{
    __shared__ float t0s[32][33];
    const int b = blockIdx.z;
    const int tblk = blockIdx.x * 32, dblk = blockIdx.y * 32;
    const int tx = threadIdx.x, ty = threadIdx.y;
    #pragma unroll
    for (int i = 0; i < 4; i++) {
        int d = dblk + ty + i * 8;
        t0s[ty + i * 8][tx] = yt[(size_t)(b * D_INNER + d) * SEQ + tblk + tx];
    }
    __syncthreads();
    #pragma unroll
    for (int i = 0; i < 4; i++) {
        int t = tblk + ty + i * 8;
        size_t row = (size_t)(b * SEQ + t);
        float z = xz[row * (2 * D_INNER) + D_INNER + dblk + tx];
        float v = t0s[tx][ty + i * 8] * silu_f(z);
        __nv_bfloat16 h = __float2bfloat16(v);
        size_t idx = row * D_INNER + dblk + tx;
        yhi[idx] = h;
        ylo[idx] = __float2bfloat16(v - __bfloat162float(h));
    }
}

__global__ void loss_kernel(const float* __restrict__ nrm, float* __restrict__ out)
{
    const int tid = threadIdx.x;
    float s = 0.f;
    #pragma unroll
    for (int i = 0; i < 4; i++) s += nrm[tid + i * 1024];
    #pragma unroll
    for (int o = 16; o > 0; o >>= 1) s += __shfl_xor_sync(0xffffffffu, s, o);
    __shared__ float sm[32];
    if ((tid & 31) == 0) sm[tid >> 5] = s;
    __syncthreads();
    if (tid == 0) {
        float t = 0.f;
        #pragma unroll
        for (int i = 0; i < 32; i++) t += sm[i];
        *out = 0.01f * t * (1.f / (float)M_ROWS);
    }
}

// ---------------------------------------------------------------------------
// Launch
// ---------------------------------------------------------------------------
extern "C" void kernel_launch(void* const* d_in, const int* in_sizes, int n_in,
                              void* d_out, int out_size)
{
    const float* x      = (const float*)d_in[0];
    const float* in_w   = (const float*)d_in[1];
    const float* in_b   = (const float*)d_in[2];
    const float* ln_g   = (const float*)d_in[3];
    const float* ln_b   = (const float*)d_in[4];
    const float* blk_ng = (const float*)d_in[5];
    const float* blk_nb = (const float*)d_in[6];
    const float* blk_ipw= (const float*)d_in[7];
    const float* blk_cw = (const float*)d_in[8];
    const float* blk_cb = (const float*)d_in[9];
    const float* blk_xpw= (const float*)d_in[10];
    const float* blk_dtw= (const float*)d_in[11];
    const float* blk_dtb= (const float*)d_in[12];
    const float* blk_Al = (const float*)d_in[13];
    const float* blk_D  = (const float*)d_in[14];
    const float* blk_opw= (const float*)d_in[15];
    const float* op_w   = (const float*)d_in[16];
    const float* op_b   = (const float*)d_in[17];
    const float* cls_w  = (const float*)d_in[18];
    const float* cls_b  = (const float*)d_in[19];
    float* out = (float*)d_out;

    float *hs, *xz, *u, *ut, *dltt, *yt, *xdbc, *nrm, *part;
    __nv_bfloat16 *lthi, *ltlo, *yhi, *ylo, *hshi, *hslo, *h2hi, *h2lo;
    __nv_bfloat16 *wihi, *wilo, *wphi, *wplo, *wohi, *wolo, *wqhi, *wqlo, *wchi, *wclo;
    cudaGetSymbolAddress((void**)&hs,   g_hl);
    cudaGetSymbolAddress((void**)&xz,   g_xz);
    cudaGetSymbolAddress((void**)&u,    g_u);
    cudaGetSymbolAddress((void**)&ut,   g_ut);
    cudaGetSymbolAddress((void**)&dltt, g_dltt);
    cudaGetSymbolAddress((void**)&yt,   g_yt);
    cudaGetSymbolAddress((void**)&xdbc, g_xdbc);
    cudaGetSymbolAddress((void**)&nrm,  g_norm);
    cudaGetSymbolAddress((void**)&part, g_part);
    cudaGetSymbolAddress((void**)&lthi, g_lthi); cudaGetSymbolAddress((void**)&ltlo, g_ltlo);
    cudaGetSymbolAddress((void**)&yhi,  g_yhi);  cudaGetSymbolAddress((void**)&ylo,  g_ylo);
    cudaGetSymbolAddress((void**)&hshi, g_hshi); cudaGetSymbolAddress((void**)&hslo, g_hslo);
    cudaGetSymbolAddress((void**)&h2hi, g_h2hi); cudaGetSymbolAddress((void**)&h2lo, g_h2lo);
    cudaGetSymbolAddress((void**)&wihi, g_wihi); cudaGetSymbolAddress((void**)&wilo, g_wilo);
    cudaGetSymbolAddress((void**)&wphi, g_wphi); cudaGetSymbolAddress((void**)&wplo, g_wplo);
    cudaGetSymbolAddress((void**)&wohi, g_wohi); cudaGetSymbolAddress((void**)&wolo, g_wolo);
    cudaGetSymbolAddress((void**)&wqhi, g_wqhi); cudaGetSymbolAddress((void**)&wqlo, g_wqlo);
    cudaGetSymbolAddress((void**)&wchi, g_wchi); cudaGetSymbolAddress((void**)&wclo, g_wclo);

    cudaFuncSetAttribute(mma_gemm<1,0>, cudaFuncAttributeMaxDynamicSharedMemorySize, MM_SMEM);
    cudaFuncSetAttribute(mma_gemm<2,0>, cudaFuncAttributeMaxDynamicSharedMemorySize, MM_SMEM);
    cudaFuncSetAttribute(mma_gemm<3,1>, cudaFuncAttributeMaxDynamicSharedMemorySize, MM_SMEM);
    cudaFuncSetAttribute(mma_gemm<4,0>, cudaFuncAttributeMaxDynamicSharedMemorySize, MM_SMEM);

    dim3 blk256(256);
    dim3 tblk(32, 8);
    dim3 tgrid(SEQ / 32, D_INNER / 32, BATCH);
    const int EP_BLOCKS = M_ROWS * 32 / 256;

    cvt_all<<<1056, blk256>>>(in_w, blk_ipw, blk_opw, op_w, cls_w,
                              wihi, wilo, wphi, wplo,
                              wohi, wolo, wqhi, wqlo, wchi, wclo);

    // in-proj: fp32 A converted on the fly, SPLIT=3 -> 4x32x3=384 CTAs
    mma_gemm<3,1><<<dim3(D_MODEL / 64, M_ROWS / 128, 3), blk256, MM_SMEM>>>(
        (const __nv_bfloat16*)x, nullptr, wihi, wilo, part, M_ROWS, D_MODEL, X_DIM);
    ep_inproj<3><<<EP_BLOCKS, blk256>>>(part, in_b, ln_g, ln_b,
                                        blk_ng, blk_nb, hs, lthi, ltlo);

    for (int l = 0; l < N_LAYERS; l++) {
        const __nv_bfloat16* pwh = wphi + (size_t)l * 2 * D_INNER * D_MODEL;
        const __nv_bfloat16* pwl = wplo + (size_t)l * 2 * D_INNER * D_MODEL;
        const __nv_bfloat16* owh = wohi + (size_t)l * D_MODEL * D_INNER;
        const __nv_bfloat16* owl = wolo + (size_t)l * D_MODEL * D_INNER;
        const float* cw  = blk_cw  + (size_t)l * D_INNER * D_CONV;
        const float* cb  = blk_cb  + (size_t)l * D_INNER;
        const float* xpw = blk_xpw + (size_t)l * 48 * D_INNER;
        const float* dtw = blk_dtw + (size_t)l * D_INNER * DT_RANK;
        const float* dtb = blk_dtb + (size_t)l * D_INNER;
        const float* Al  = blk_Al  + (size_t)l * D_INNER * D_STATE;
        const float* Dp  = blk_D   + (size_t)l * D_INNER;

        // ipw: 16x32 = 512 CTAs
        mma_gemm<1,0><<<dim3(2 * D_INNER / 64, M_ROWS / 128, 1), blk256, MM_SMEM>>>(
            lthi, ltlo, pwh, pwl, xz, M_ROWS, 2 * D_INNER, D_MODEL);
        conv2_kernel<<<tgrid, tblk>>>(xz, cw, cb, u, ut);
        gemm_xpw<<<dim3(1, M_ROWS / 128, 4), blk256>>>(
            u, xpw, part, M_ROWS, 48, D_INNER, 4);
        reduce_k<4,0><<<(M_ROWS * 48 / 4 + 255) / 256, blk256>>>(
            part, nullptr, xdbc, M_ROWS * 48, 48);
        deltaT_kernel<<<tgrid, tblk>>>(xdbc, dtw, dtb, dltt);
        scan_fused<<<NGROUP, blk256>>>(dltt, ut, xdbc, Al, Dp, yt);
        gate_kernel<<<tgrid, tblk>>>(yt, xz, yhi, ylo);
        // opw: 4x32x4 = 512 CTAs
        mma_gemm<4,0><<<dim3(D_MODEL / 64, M_ROWS / 128, 4), blk256, MM_SMEM>>>(
            yhi, ylo, owh, owl, part, M_ROWS, D_MODEL, D_INNER);
        if (l + 1 < N_LAYERS) {
            ep_opw<4,1><<<EP_BLOCKS, blk256>>>(part,
                blk_ng + (size_t)(l + 1) * D_MODEL,
                blk_nb + (size_t)(l + 1) * D_MODEL, hs, lthi, ltlo);
        } else {
            ep_opw<4,0><<<EP_BLOCKS, blk256>>>(part, nullptr, nullptr, hs, hshi, hslo);
        }
    }

    // head: 4x32x4 = 512 CTAs
    mma_gemm<4,0><<<dim3(D_MODEL / 64, M_ROWS / 128, 4), blk256, MM_SMEM>>>(
        hshi, hslo, wqhi, wqlo, part, M_ROWS, D_MODEL, D_MODEL);
    ep_head<4><<<EP_BLOCKS, blk256>>>(part, op_b, h2hi, h2lo, nrm);
    // cls: 2x32x4 = 256 CTAs
    mma_gemm<4,0><<<dim3(N_CLS / 64, M_ROWS / 128, 4), blk256, MM_SMEM>>>(
        h2hi, h2lo, wchi, wclo, part, M_ROWS, N_CLS, D_MODEL);
    reduce_k<4,1><<<(M_ROWS * N_CLS / 4 + 255) / 256, blk256>>>(
        part, cls_b, out, M_ROWS * N_CLS, N_CLS);
    loss_kernel<<<1, 1024>>>(nrm, out + (out_size - 1));
}

// round 17
// speedup vs baseline: 1.5449x; 1.5449x over previous
#include <cuda_runtime.h>
#include <cuda_bf16.h>
#include <math.h>

#define BATCH    4
#define SEQ      1024
#define M_ROWS   4096
#define D_MODEL  256
#define D_INNER  512
#define D_STATE  16
#define DT_RANK  16
#define D_CONV   4
#define N_LAYERS 2
#define X_DIM    768
#define N_CLS    128

#define NCHUNK   16
#define CHUNK    64
#define NGROUP   (BATCH * D_INNER)

typedef unsigned int u32;
typedef unsigned short u16;

// ---------------------------------------------------------------------------
// Scratch (fp32)
// ---------------------------------------------------------------------------
__device__ float g_hl  [M_ROWS * D_MODEL];
__device__ float g_xz  [M_ROWS * 2 * D_INNER];
__device__ float g_u   [M_ROWS * D_INNER];
__device__ float g_ut  [M_ROWS * D_INNER];
__device__ float g_dltt[M_ROWS * D_INNER];
__device__ float g_yt  [M_ROWS * D_INNER];
__device__ float g_xdbc[M_ROWS * 48];
__device__ float g_norm[M_ROWS];
__device__ float g_part[4 * M_ROWS * D_MODEL];

// bf16 hi/lo operand buffers
__device__ __nv_bfloat16 g_lthi[M_ROWS * D_MODEL], g_ltlo[M_ROWS * D_MODEL];
__device__ __nv_bfloat16 g_yhi [M_ROWS * D_INNER], g_ylo [M_ROWS * D_INNER];
__device__ __nv_bfloat16 g_hshi[M_ROWS * D_MODEL], g_hslo[M_ROWS * D_MODEL];
__device__ __nv_bfloat16 g_h2hi[M_ROWS * D_MODEL], g_h2lo[M_ROWS * D_MODEL];
__device__ __nv_bfloat16 g_wihi[D_MODEL * X_DIM],  g_wilo[D_MODEL * X_DIM];
__device__ __nv_bfloat16 g_wphi[N_LAYERS * 2 * D_INNER * D_MODEL], g_wplo[N_LAYERS * 2 * D_INNER * D_MODEL];
__device__ __nv_bfloat16 g_wohi[N_LAYERS * D_MODEL * D_INNER],     g_wolo[N_LAYERS * D_MODEL * D_INNER];
__device__ __nv_bfloat16 g_wqhi[D_MODEL * D_MODEL], g_wqlo[D_MODEL * D_MODEL];
__device__ __nv_bfloat16 g_wchi[N_CLS * D_MODEL],   g_wclo[N_CLS * D_MODEL];

__device__ __forceinline__ float gelu_f(float v) {
    return 0.5f * v * (1.f + erff(v * 0.70710678118654752f));
}
__device__ __forceinline__ float silu_f(float v) {
    return v / (1.f + __expf(-v));
}
__device__ __forceinline__ u32 s2u(const void* p) {
    u32 a;
    asm("{ .reg .u64 t; cvta.to.shared.u64 t, %1; cvt.u32.u64 %0, t; }" : "=r"(a) : "l"(p));
    return a;
}

// ---------------------------------------------------------------------------
// Warp-MMA primitives
// ---------------------------------------------------------------------------
#define LDSM4(r, addr) \
    asm volatile("ldmatrix.sync.aligned.m8n8.x4.shared.b16 {%0,%1,%2,%3}, [%4];" \
        : "=r"((r)[0]), "=r"((r)[1]), "=r"((r)[2]), "=r"((r)[3]) : "r"(addr))

#define MMA16816(c, a, b0, b1) \
    asm volatile("mma.sync.aligned.m16n8k16.row.col.f32.bf16.bf16.f32 " \
        "{%0,%1,%2,%3}, {%4,%5,%6,%7}, {%8,%9}, {%0,%1,%2,%3};" \
        : "+f"((c)[0]), "+f"((c)[1]), "+f"((c)[2]), "+f"((c)[3]) \
        : "r"((a)[0]), "r"((a)[1]), "r"((a)[2]), "r"((a)[3]), "r"(b0), "r"(b1))

#define CPA(s, g)  asm volatile("cp.async.cg.shared.global [%0], [%1], 16;" :: "r"(s), "l"(g))
#define CPC()      asm volatile("cp.async.commit_group;" ::: "memory")
#define CPW0()     asm volatile("cp.async.wait_group 0;" ::: "memory")
#define CPW1()     asm volatile("cp.async.wait_group 1;" ::: "memory")

// smem tensor block: 128 rows x 64B. XOR swizzle on 16B units:
// x = u ^ ((row>>1)&3) -> conflict-free ldmatrix + stores.
#define TBYTES 8192
#define MM_SMEM (2 * 4 * TBYTES)
#define SWZ_OFF(row, u) ((u32)((row) * 64 + ((((u) ^ (((row) >> 1) & 3)) & 3) << 4)))

// fp32 -> (bf16 hi, bf16 lo)
__device__ __forceinline__ void bf16_hilo4(const float4& v,
                                           __nv_bfloat16* hi, __nv_bfloat16* lo)
{
    __nv_bfloat16 h0 = __float2bfloat16(v.x), h1 = __float2bfloat16(v.y);
    __nv_bfloat16 h2 = __float2bfloat16(v.z), h3 = __float2bfloat16(v.w);
    hi[0] = h0; hi[1] = h1; hi[2] = h2; hi[3] = h3;
    lo[0] = __float2bfloat16(v.x - __bfloat162float(h0));
    lo[1] = __float2bfloat16(v.y - __bfloat162float(h1));
    lo[2] = __float2bfloat16(v.z - __bfloat162float(h2));
    lo[3] = __float2bfloat16(v.w - __bfloat162float(h3));
}

// ---------------------------------------------------------------------------
// Split-bf16 tensor-core GEMM (hi*hi + hi*lo + lo*hi), 128x128 tile, BK=32.
// CVTA=1: Ahi is const float* (fp32 A converted on the fly; Alo ignored).
// ---------------------------------------------------------------------------
template<int SPLIT, int CVTA>
__global__ __launch_bounds__(256) void mma_gemm(
    const __nv_bfloat16* __restrict__ Ahi, const __nv_bfloat16* __restrict__ Alo,
    const __nv_bfloat16* __restrict__ Bhi, const __nv_bfloat16* __restrict__ Blo,
    float* __restrict__ C, int M, int N, int K)
{
    extern __shared__ u16 sm[];
    const int tid  = threadIdx.x;
    const int wid  = tid >> 5;
    const int lane = tid & 31;
    const int m0 = blockIdx.y * 128, n0 = blockIdx.x * 128;
    const int Kc = K / SPLIT;
    const int kbeg = blockIdx.z * Kc;
    const u32 sbase = s2u(sm);
    char* smc = (char*)sm;

    const float* Af = (const float*)Ahi;
    const __nv_bfloat16* gpA[2] = {Ahi + (size_t)m0 * K + kbeg, Alo + (size_t)m0 * K + kbeg};
    const __nv_bfloat16* gpB[2] = {Bhi + (size_t)n0 * K + kbeg, Blo + (size_t)n0 * K + kbeg};

    const int wm0 = (wid & 3) * 32;
    const int wn0 = (wid >> 2) * 64;

    float acc[2][8][4];
    #pragma unroll
    for (int i = 0; i < 2; i++)
        #pragma unroll
        for (int j = 0; j < 8; j++)
            #pragma unroll
            for (int q = 0; q < 4; q++) acc[i][j][q] = 0.f;

    const int nch = Kc / 32;

    if (CVTA) {
        #pragma unroll
        for (int i = 0; i < 2; i++) {
            int idx = tid + i * 256;
            int row = idx >> 2, u = idx & 3;
            const float* src = Af + (size_t)(m0 + row) * K + kbeg + u * 8;
            float4 v0 = *(const float4*)src;
            float4 v1 = *(const float4*)(src + 4);
            __align__(16) __nv_bfloat16 hi[8], lo[8];
            bf16_hilo4(v0, hi, lo); bf16_hilo4(v1, hi + 4, lo + 4);
            u32 off = SWZ_OFF(row, u);
            *(uint4*)(smc + off) = *(uint4*)hi;
            *(uint4*)(smc + TBYTES + off) = *(uint4*)lo;
        }
        #pragma unroll
        for (int i = 0; i < 4; i++) {
            int idx = tid + i * 256;
            int tno = idx >> 9, unit = idx & 511;
            int row = unit >> 2, u = unit & 3;
            u32 s = sbase + (u32)((2 + tno) * TBYTES) + SWZ_OFF(row, u);
            CPA(s, (const void*)(gpB[tno] + (size_t)row * K + u * 8));
        }
    } else {
        #pragma unroll
        for (int i = 0; i < 8; i++) {
            int idx = tid + i * 256;
            int tno = idx >> 9, unit = idx & 511;
            int row = unit >> 2, u = unit & 3;
            const __nv_bfloat16* g = (tno < 2) ? gpA[tno] : gpB[tno - 2];
            u32 s = sbase + (u32)(tno * TBYTES) + SWZ_OFF(row, u);
            CPA(s, (const void*)(g + (size_t)row * K + u * 8));
        }
    }
    CPC();

    for (int c = 0; c < nch; c++) {
        const int b = c & 1;
        float4 av[4];
        if (c + 1 < nch) {
            const int k0 = (c + 1) * 32;
            const u32 bb = (u32)((b ^ 1) * 4 * TBYTES);
            if (CVTA) {
                #pragma unroll
                for (int i = 0; i < 2; i++) {
                    int idx = tid + i * 256;
                    int row = idx >> 2, u = idx & 3;
                    const float* src = Af + (size_t)(m0 + row) * K + kbeg + k0 + u * 8;
                    av[i * 2 + 0] = *(const float4*)src;
                    av[i * 2 + 1] = *(const float4*)(src + 4);
                }
                #pragma unroll
                for (int i = 0; i < 4; i++) {
                    int idx = tid + i * 256;
                    int tno = idx >> 9, unit = idx & 511;
                    int row = unit >> 2, u = unit & 3;
                    u32 s = sbase + bb + (u32)((2 + tno) * TBYTES) + SWZ_OFF(row, u);
                    CPA(s, (const void*)(gpB[tno] + (size_t)row * K + k0 + u * 8));
                }
            } else {
                #pragma unroll
                for (int i = 0; i < 8; i++) {
                    int idx = tid + i * 256;
                    int tno = idx >> 9, unit = idx & 511;
                    int row = unit >> 2, u = unit & 3;
                    const __nv_bfloat16* g = (tno < 2) ? gpA[tno] : gpB[tno - 2];
                    u32 s = sbase + bb + (u32)(tno * TBYTES) + SWZ_OFF(row, u);
                    CPA(s, (const void*)(g + (size_t)row * K + k0 + u * 8));
                }
            }
            CPC();
            CPW1();
        } else {
            CPW0();
        }
        __syncthreads();

        const u32 base = sbase + (u32)(b * 4 * TBYTES);
        #pragma unroll
        for (int kk = 0; kk < 32; kk += 16) {
            const int id = lane >> 3;
            u32 ah[2][4], al[2][4];
            #pragma unroll
            for (int mt = 0; mt < 2; mt++) {
                int lrow = wm0 + mt * 16 + ((id & 1) << 3) + (lane & 7);
                int au = (kk >> 3) + (id >> 1);
                u32 off = SWZ_OFF(lrow, au);
                LDSM4(ah[mt], base + off);
                LDSM4(al[mt], base + (u32)TBYTES + off);
            }
            u32 bh[4][4], bl[4][4];
            #pragma unroll
            for (int p = 0; p < 4; p++) {
                int brow = wn0 + (2 * p + (id >> 1)) * 8 + (lane & 7);
                int bu = (kk >> 3) + (id & 1);
                u32 off = SWZ_OFF(brow, bu);
                LDSM4(bh[p], base + (u32)(2 * TBYTES) + off);
                LDSM4(bl[p], base + (u32)(3 * TBYTES) + off);
            }
            #pragma unroll
            for (int mt = 0; mt < 2; mt++)
                #pragma unroll
                for (int nt = 0; nt < 8; nt++) {
                    const int p = nt >> 1, o = (nt & 1) * 2;
                    MMA16816(acc[mt][nt], ah[mt], bh[p][o], bh[p][o + 1]);
                    MMA16816(acc[mt][nt], ah[mt], bl[p][o], bl[p][o + 1]);
                    MMA16816(acc[mt][nt], al[mt], bh[p][o], bh[p][o + 1]);
                }
        }
        if (CVTA && c + 1 < nch) {
            char* bb = smc + (b ^ 1) * 4 * TBYTES;
            #pragma unroll
            for (int i = 0; i < 2; i++) {
                int idx = tid + i * 256;
                int row = idx >> 2, u = idx & 3;
                __align__(16) __nv_bfloat16 hi[8], lo[8];
                bf16_hilo4(av[i * 2 + 0], hi, lo);
                bf16_hilo4(av[i * 2 + 1], hi + 4, lo + 4);
                u32 off = SWZ_OFF(row, u);
                *(uint4*)(bb + off) = *(uint4*)hi;
                *(uint4*)(bb + TBYTES + off) = *(uint4*)lo;
            }
        }
        __syncthreads();
    }

    float* Cout = (SPLIT > 1) ? (C + (size_t)blockIdx.z * M * N) : C;
    #pragma unroll
    for (int mt = 0; mt < 2; mt++) {
        const int row = m0 + wm0 + mt * 16 + (lane >> 2);
        #pragma unroll
        for (int nt = 0; nt < 8; nt++) {
            const int col = n0 + wn0 + nt * 8 + (lane & 3) * 2;
            *(float2*)(Cout + (size_t)row * N + col) =
                make_float2(acc[mt][nt][0], acc[mt][nt][1]);
            *(float2*)(Cout + (size_t)(row + 8) * N + col) =
                make_float2(acc[mt][nt][2], acc[mt][nt][3]);
        }
    }
}

// ---------------------------------------------------------------------------
// Batched weight conversion: 5 tensors, 1 launch.
// ---------------------------------------------------------------------------
#define CV_N1 (D_MODEL * X_DIM)
#define CV_N2 (N_LAYERS * 2 * D_INNER * D_MODEL)
#define CV_N3 (N_LAYERS * D_MODEL * D_INNER)
#define CV_N4 (D_MODEL * D_MODEL)
#define CV_N5 (N_CLS * D_MODEL)
#define CV_TOT (CV_N1 + CV_N2 + CV_N3 + CV_N4 + CV_N5)

__global__ void cvt_all(const float* __restrict__ s1,
                        const float* __restrict__ s2, const float* __restrict__ s3,
                        const float* __restrict__ s4, const float* __restrict__ s5,
                        __nv_bfloat16* h1, __nv_bfloat16* l1,
                        __nv_bfloat16* h2, __nv_bfloat16* l2,
                        __nv_bfloat16* h3, __nv_bfloat16* l3,
                        __nv_bfloat16* h4, __nv_bfloat16* l4,
                        __nv_bfloat16* h5, __nv_bfloat16* l5)
{
    int gi = (blockIdx.x * blockDim.x + threadIdx.x) * 4;
    const int stride = gridDim.x * blockDim.x * 4;
    for (; gi < CV_TOT; gi += stride) {
        const float* src; __nv_bfloat16 *hi, *lo; int off = gi;
        if (off < CV_N1) { src = s1; hi = h1; lo = l1; }
        else if ((off -= CV_N1) < CV_N2) { src = s2; hi = h2; lo = l2; }
        else if ((off -= CV_N2) < CV_N3) { src = s3; hi = h3; lo = l3; }
        else if ((off -= CV_N3) < CV_N4) { src = s4; hi = h4; lo = l4; }
        else { off -= CV_N4; src = s5; hi = h5; lo = l5; }
        float4 v = *(const float4*)(src + off);
        bf16_hilo4(v, hi + off, lo + off);
    }
}

// ---------------------------------------------------------------------------
// xpw GEMM (N=48) FFMA split-K
// ---------------------------------------------------------------------------
__global__ __launch_bounds__(256) void gemm_xpw(
    const float* __restrict__ A, const float* __restrict__ W,
    float* __restrict__ Cp, int M, int N, int K, int splitK)
{
    __shared__ float As[16][132];
    __shared__ float Ws[16][68];
    const int tid = threadIdx.x;
    const int m0 = blockIdx.y * 128;
    const int Kc = K / splitK;
    const int kbeg = blockIdx.z * Kc;
    const int tm = tid >> 4;
    const int tn = tid & 15;
    const int lr = tid >> 2;
    const int lc = (tid & 3) * 4;

    float acc[8][4] = {};

    for (int k0 = kbeg; k0 < kbeg + Kc; k0 += 16) {
        #pragma unroll
        for (int i = 0; i < 2; i++) {
            int r = lr + i * 64;
            float4 v = *(const float4*)(A + (size_t)(m0 + r) * K + k0 + lc);
            As[lc + 0][r] = v.x; As[lc + 1][r] = v.y;
            As[lc + 2][r] = v.z; As[lc + 3][r] = v.w;
        }
        {
            float4 v = make_float4(0.f, 0.f, 0.f, 0.f);
            if (lr < N)
                v = *(const float4*)(W + (size_t)lr * K + k0 + lc);
            Ws[lc + 0][lr] = v.x; Ws[lc + 1][lr] = v.y;
            Ws[lc + 2][lr] = v.z; Ws[lc + 3][lr] = v.w;
        }
        __syncthreads();
        #pragma unroll
        for (int kk = 0; kk < 16; kk++) {
            float a[8], b[4];
            *(float4*)&a[0] = *(const float4*)&As[kk][tm * 8];
            *(float4*)&a[4] = *(const float4*)&As[kk][tm * 8 + 4];
            *(float4*)&b[0] = *(const float4*)&Ws[kk][tn * 4];
            #pragma unroll
            for (int i = 0; i < 8; i++)
                #pragma unroll
                for (int j = 0; j < 4; j++)
                    acc[i][j] = fmaf(a[i], b[j], acc[i][j]);
        }
        __syncthreads();
    }

    const int n = tn * 4;
    if (n >= N) return;
    float* Cout = Cp + (size_t)blockIdx.z * M * N;
    #pragma unroll
    for (int i = 0; i < 8; i++) {
        int m = m0 + tm * 8 + i;
        float4 v = {acc[i][0], acc[i][1], acc[i][2], acc[i][3]};
        *(float4*)(Cout + (size_t)m * N + n) = v;
    }
}

template<int S, int BIAS>
__global__ void reduce_k(const float* __restrict__ part, const float* __restrict__ bias,
                         float* __restrict__ out, int MN, int N)
{
    int i4 = (blockIdx.x * blockDim.x + threadIdx.x) * 4;
    if (i4 >= MN) return;
    float4 v = *(const float4*)(part + i4);
    #pragma unroll
    for (int s = 1; s < S; s++) {
        float4 p = *(const float4*)(part + (size_t)s * MN + i4);
        v.x += p.x; v.y += p.y; v.z += p.z; v.w += p.w;
    }
    if (BIAS) {
        float4 bv = *(const float4*)(bias + (i4 % N));
        v.x += bv.x; v.y += bv.y; v.z += bv.z; v.w += bv.w;
    }
    *(float4*)(out + i4) = v;
}

// ---------------------------------------------------------------------------
// Warp-per-row epilogues
// ---------------------------------------------------------------------------
__device__ __forceinline__ void warp_stats(const float4& v0, const float4& v1,
                                           float& mu, float& rstd)
{
    float s1 = v0.x + v0.y + v0.z + v0.w + v1.x + v1.y + v1.z + v1.w;
    float s2 = v0.x*v0.x + v0.y*v0.y + v0.z*v0.z + v0.w*v0.w
             + v1.x*v1.x + v1.y*v1.y + v1.z*v1.z + v1.w*v1.w;
    #pragma unroll
    for (int o = 16; o > 0; o >>= 1) {
        s1 += __shfl_xor_sync(0xffffffffu, s1, o);
        s2 += __shfl_xor_sync(0xffffffffu, s2, o);
    }
    mu = s1 * (1.f / 256.f);
    rstd = rsqrtf(s2 * (1.f / 256.f) - mu * mu + 1e-5f);
}
__device__ __forceinline__ float4 ln_apply4(const float4& v, float mu, float rstd,
                                            const float4& g, const float4& b)
{
    float4 o;
    o.x = (v.x - mu) * rstd * g.x + b.x;
    o.y = (v.y - mu) * rstd * g.y + b.y;
    o.z = (v.z - mu) * rstd * g.z + b.z;
    o.w = (v.w - mu) * rstd * g.w + b.w;
    return o;
}
__device__ __forceinline__ float4 gelu4(float4 v) {
    v.x = gelu_f(v.x); v.y = gelu_f(v.y); v.z = gelu_f(v.z); v.w = gelu_f(v.w);
    return v;
}
__device__ __forceinline__ void add4(float4& a, const float4& b) {
    a.x += b.x; a.y += b.y; a.z += b.z; a.w += b.w;
}

template<int S>
__global__ void ep_inproj(const float* __restrict__ part, const float* __restrict__ bias,
                          const float* __restrict__ lng, const float* __restrict__ lnb,
                          const float* __restrict__ ng0, const float* __restrict__ nb0,
                          float* __restrict__ hs,
                          __nv_bfloat16* __restrict__ lthi, __nv_bfloat16* __restrict__ ltlo)
{
    const int gi = blockIdx.x * blockDim.x + threadIdx.x;
    const int row = gi >> 5;
    const int lane = gi & 31;
    const int MN = M_ROWS * D_MODEL;
    const int c0 = lane * 4, c1 = 128 + lane * 4;
    const size_t i0 = (size_t)row * D_MODEL + c0;
    const size_t i1 = (size_t)row * D_MODEL + c1;
    float4 v0 = *(const float4*)(part + i0);
    float4 v1 = *(const float4*)(part + i1);
    #pragma unroll
    for (int s = 1; s < S; s++) {
        add4(v0, *(const float4*)(part + (size_t)s * MN + i0));
        add4(v1, *(const float4*)(part + (size_t)s * MN + i1));
    }
    add4(v0, *(const float4*)(bias + c0));
    add4(v1, *(const float4*)(bias + c1));
    float mu, rstd;
    warp_stats(v0, v1, mu, rstd);
    float4 g0 = *(const float4*)(lng + c0), g1 = *(const float4*)(lng + c1);
    float4 bb0 = *(const float4*)(lnb + c0), bb1 = *(const float4*)(lnb + c1);
    float4 w0 = gelu4(ln_apply4(v0, mu, rstd, g0, bb0));
    float4 w1 = gelu4(ln_apply4(v1, mu, rstd, g1, bb1));
    *(float4*)(hs + i0) = w0;
    *(float4*)(hs + i1) = w1;
    warp_stats(w0, w1, mu, rstd);
    g0 = *(const float4*)(ng0 + c0); g1 = *(const float4*)(ng0 + c1);
    bb0 = *(const float4*)(nb0 + c0); bb1 = *(const float4*)(nb0 + c1);
    float4 t0 = ln_apply4(w0, mu, rstd, g0, bb0);
    float4 t1 = ln_apply4(w1, mu, rstd, g1, bb1);
    bf16_hilo4(t0, lthi + i0, ltlo + i0);
    bf16_hilo4(t1, lthi + i1, ltlo + i1);
}

template<int S, int LN>
__global__ void ep_opw(const float* __restrict__ part, const float* __restrict__ ng,
                       const float* __restrict__ nb, float* __restrict__ hs,
                       __nv_bfloat16* __restrict__ ohi, __nv_bfloat16* __restrict__ olo)
{
    const int gi = blockIdx.x * blockDim.x + threadIdx.x;
    const int row = gi >> 5;
    const int lane = gi & 31;
    const int MN = M_ROWS * D_MODEL;
    const int c0 = lane * 4, c1 = 128 + lane * 4;
    const size_t i0 = (size_t)row * D_MODEL + c0;
    const size_t i1 = (size_t)row * D_MODEL + c1;
    float4 v0 = *(const float4*)(hs + i0);
    float4 v1 = *(const float4*)(hs + i1);
    #pragma unroll
    for (int s = 0; s < S; s++) {
        add4(v0, *(const float4*)(part + (size_t)s * MN + i0));
        add4(v1, *(const float4*)(part + (size_t)s * MN + i1));
    }
    *(float4*)(hs + i0) = v0;
    *(float4*)(hs + i1) = v1;
    if (LN) {
        float mu, rstd;
        warp_stats(v0, v1, mu, rstd);
        float4 g0 = *(const float4*)(ng + c0), g1 = *(const float4*)(ng + c1);
        float4 b0 = *(const float4*)(nb + c0), b1 = *(const float4*)(nb + c1);
        float4 t0 = ln_apply4(v0, mu, rstd, g0, b0);
        float4 t1 = ln_apply4(v1, mu, rstd, g1, b1);
        bf16_hilo4(t0, ohi + i0, olo + i0);
        bf16_hilo4(t1, ohi + i1, olo + i1);
    } else {
        bf16_hilo4(v0, ohi + i0, olo + i0);
        bf16_hilo4(v1, ohi + i1, olo + i1);
    }
}

template<int S>
__global__ void ep_head(const float* __restrict__ part, const float* __restrict__ bias,
                        __nv_bfloat16* __restrict__ h2hi, __nv_bfloat16* __restrict__ h2lo,
                        float* __restrict__ nrm)
{
    const int gi = blockIdx.x * blockDim.x + threadIdx.x;
    const int row = gi >> 5;
    const int lane = gi & 31;
    const int MN = M_ROWS * D_MODEL;
    const int c0 = lane * 4, c1 = 128 + lane * 4;
    const size_t i0 = (size_t)row * D_MODEL + c0;
    const size_t i1 = (size_t)row * D_MODEL + c1;
    float4 v0 = *(const float4*)(part + i0);
    float4 v1 = *(const float4*)(part + i1);
    #pragma unroll
    for (int s = 1; s < S; s++) {
        add4(v0, *(const float4*)(part + (size_t)s * MN + i0));
        add4(v1, *(const float4*)(part + (size_t)s * MN + i1));
    }
    add4(v0, *(const float4*)(bias + c0));
    add4(v1, *(const float4*)(bias + c1));
    v0 = gelu4(v0); v1 = gelu4(v1);
    bf16_hilo4(v0, h2hi + i0, h2lo + i0);
    bf16_hilo4(v1, h2hi + i1, h2lo + i1);
    float s = v0.x*v0.x + v0.y*v0.y + v0.z*v0.z + v0.w*v0.w
            + v1.x*v1.x + v1.y*v1.y + v1.z*v1.z + v1.w*v1.w;
    #pragma unroll
    for (int o = 16; o > 0; o >>= 1) s += __shfl_xor_sync(0xffffffffu, s, o);
    if (lane == 0) nrm[row] = sqrtf(s);
}

// ---------------------------------------------------------------------------
// Depthwise causal conv (k=4) + SiLU -> u and ut
// ---------------------------------------------------------------------------
__global__ void conv2_kernel(const float* __restrict__ xz, const float* __restrict__ cw,
                             const float* __restrict__ cb, float* __restrict__ u,
                             float* __restrict__ ut)
{
    __shared__ float tile[32][33];
    const int b = blockIdx.z;
    const int t0 = blockIdx.x * 32, d0 = blockIdx.y * 32;
    const int tx = threadIdx.x, ty = threadIdx.y;
    const int d = d0 + tx;
    const float w0 = cw[d * 4 + 0], w1 = cw[d * 4 + 1];
    const float w2 = cw[d * 4 + 2], w3 = cw[d * 4 + 3];
    const float bb = cb[d];
    #pragma unroll
    for (int i = 0; i < 4; i++) {
        const int t = t0 + ty + i * 8;
        const size_t rbase = (size_t)(b * SEQ + t) * (2 * D_INNER) + d;
        float acc = bb;
        if (t >= 3) {
            acc = fmaf(w0, xz[rbase - 3 * 2 * D_INNER], acc);
            acc = fmaf(w1, xz[rbase - 2 * 2 * D_INNER], acc);
            acc = fmaf(w2, xz[rbase - 1 * 2 * D_INNER], acc);
        } else {
            if (t >= 2) acc = fmaf(w1, xz[rbase - 2 * 2 * D_INNER], acc);
            if (t >= 1) acc = fmaf(w2, xz[rbase - 1 * 2 * D_INNER], acc);
        }
        acc = fmaf(w3, xz[rbase], acc);
        acc = silu_f(acc);
        u[(size_t)(b * SEQ + t) * D_INNER + d] = acc;
        tile[ty + i * 8][tx] = acc;
    }
    __syncthreads();
    #pragma unroll
    for (int i = 0; i < 4; i++) {
        const int dd = d0 + ty + i * 8;
        ut[(size_t)(b * D_INNER + dd) * SEQ + t0 + tx] = tile[tx][ty + i * 8];
    }
}

// ---------------------------------------------------------------------------
// delta = softplus(dt @ dtw^T + dtb) -> dltt [b][d][t]
// ---------------------------------------------------------------------------
__global__ void deltaT_kernel(const float* __restrict__ xdbc, const float* __restrict__ dtw,
                              const float* __restrict__ dtb, float* __restrict__ dltt)
{
    __shared__ float w_s[32][17];
    __shared__ float b_s[32];
    __shared__ float tile[32][33];
    const int b = blockIdx.z;
    const int t0 = blockIdx.x * 32, d0 = blockIdx.y * 32;
    const int tx = threadIdx.x, ty = threadIdx.y;
    const int tid = ty * 32 + tx;
    {
        int r = tid >> 4, c = tid & 15;
        w_s[r][c] = dtw[(d0 + r) * DT_RANK + c];
        w_s[r + 16][c] = dtw[(d0 + r + 16) * DT_RANK + c];
        if (tid < 32) b_s[tid] = dtb[d0 + tid];
    }
    __syncthreads();
    #pragma unroll
    for (int i = 0; i < 4; i++) {
        const int t = t0 + ty + i * 8;
        const float* xr = xdbc + (size_t)(b * SEQ + t) * 48;
        float acc = b_s[tx];
        #pragma unroll
        for (int r = 0; r < DT_RANK; r++)
            acc = fmaf(__ldg(xr + r), w_s[tx][r], acc);
        tile[ty + i * 8][tx] = (acc > 20.f) ? acc : log1pf(__expf(acc));
    }
    __syncthreads();
    #pragma unroll
    for (int i = 0; i < 4; i++) {
        const int dd = d0 + ty + i * 8;
        dltt[(size_t)(b * D_INNER + dd) * SEQ + t0 + tx] = tile[tx][ty + i * 8];
    }
}

// ---------------------------------------------------------------------------
// Fused chunked selective scan (small smem, high occupancy)
// ---------------------------------------------------------------------------
__global__ __launch_bounds__(256) void scan_fused(
    const float* __restrict__ dltt, const float* __restrict__ ut,
    const float* __restrict__ xdbc, const float* __restrict__ A_log,
    const float* __restrict__ Dp, float* __restrict__ yt)
{
    __shared__ float Ps[NCHUNK][D_STATE];
    __shared__ float Qs[NCHUNK][D_STATE];
    __shared__ float Ts[NCHUNK][D_STATE];
    const int tid = threadIdx.x;
    const int g = blockIdx.x;
    const int c = tid >> 4;
    const int n = tid & 15;
    const int b = g >> 9;
    const int d = g & (D_INNER - 1);
    const float A  = -__expf(A_log[d * D_STATE + n]);
    const float Dd = Dp[d];
    const size_t base = (size_t)g * SEQ + c * CHUNK;
    const float* xb = xdbc + ((size_t)b * SEQ + c * CHUNK) * 48 + DT_RANK;

    float dt[16], uu[16];
    if (c < NCHUNK - 1) {
        float s = 0.f, sumd = 0.f;
        for (int tc = 0; tc < CHUNK; tc += 16) {
            #pragma unroll
            for (int q = 0; q < 4; q++) {
                float4 v = ((const float4*)(dltt + base + tc))[q];
                dt[q*4+0] = v.x; dt[q*4+1] = v.y; dt[q*4+2] = v.z; dt[q*4+3] = v.w;
                float4 w = ((const float4*)(ut + base + tc))[q];
                uu[q*4+0] = w.x; uu[q*4+1] = w.y; uu[q*4+2] = w.z; uu[q*4+3] = w.w;
            }
            #pragma unroll
            for (int j = 0; j < 16; j++) {
                const float Bn = __ldg(xb + (size_t)(tc + j) * 48 + n);
                s = fmaf(s, __expf(dt[j] * A), dt[j] * uu[j] * Bn);
                sumd += dt[j];
            }
        }
        Qs[c][n] = s;
        Ps[c][n] = __expf(A * sumd);
    }
    __syncthreads();

    if (tid < D_STATE) {
        float t = 0.f;
        Ts[0][tid] = 0.f;
        #pragma unroll
        for (int cc = 1; cc < NCHUNK; cc++) {
            t = fmaf(Ps[cc - 1][tid], t, Qs[cc - 1][tid]);
            Ts[cc][tid] = t;
        }
    }
    __syncthreads();

    {
        float s = Ts[c][n];
        for (int tc = 0; tc < CHUNK; tc += 16) {
            #pragma unroll
            for (int q = 0; q < 4; q++) {
                float4 v = ((const float4*)(dltt + base + tc))[q];
                dt[q*4+0] = v.x; dt[q*4+1] = v.y; dt[q*4+2] = v.z; dt[q*4+3] = v.w;
                float4 w = ((const float4*)(ut + base + tc))[q];
                uu[q*4+0] = w.x; uu[q*4+1] = w.y; uu[q*4+2] = w.z; uu[q*4+3] = w.w;
            }
            float rv = 0.f;
            #pragma unroll
            for (int j = 0; j < 16; j++) {
                const float* xr = xb + (size_t)(tc + j) * 48;
                const float Bn = __ldg(xr + n);
                const float Cn = __ldg(xr + D_STATE + n);
                s = fmaf(s, __expf(dt[j] * A), dt[j] * uu[j] * Bn);
                float v = s * Cn;
                #pragma unroll
                for (int o = 8; o > 0; o >>= 1) v += __shfl_xor_sync(0xffffffffu, v, o);
                if (n == j) rv = v + uu[j] * Dd;
            }
            yt[base + tc + n] = rv;
        }
    }
}

// ---------------------------------------------------------------------------
// Gate + transpose -> y hi/lo
// ---------------------------------------------------------------------------
__global__ void gate_kernel(const float* __restrict__ yt, const float* __restrict__ xz,
                            __nv_bfloat16* __restrict__ yhi, __nv_bfloat16* __restrict__ ylo)
{
    __shared__ float t0s[32][33];
    const int b = blockIdx.z;
    const int tblk = blockIdx.x * 32, dblk = blockIdx.y * 32;
    const int tx = threadIdx.x, ty = threadIdx.y;
    #pragma unroll
    for (int i = 0; i < 4; i++) {
        int d = dblk + ty + i * 8;
        t0s[ty + i * 8][tx] = yt[(size_t)(b * D_INNER + d) * SEQ + tblk + tx];
    }
    __syncthreads();
    #pragma unroll
    for (int i = 0; i < 4; i++) {
        int t = tblk + ty + i * 8;
        size_t row = (size_t)(b * SEQ + t);
        float z = xz[row * (2 * D_INNER) + D_INNER + dblk + tx];
        float v = t0s[tx][ty + i * 8] * silu_f(z);
        __nv_bfloat16 h = __float2bfloat16(v);
        size_t idx = row * D_INNER + dblk + tx;
        yhi[idx] = h;
        ylo[idx] = __float2bfloat16(v - __bfloat162float(h));
    }
}

__global__ void loss_kernel(const float* __restrict__ nrm, float* __restrict__ out)
{
    const int tid = threadIdx.x;
    float s = 0.f;
    #pragma unroll
    for (int i = 0; i < 4; i++) s += nrm[tid + i * 1024];
    #pragma unroll
    for (int o = 16; o > 0; o >>= 1) s += __shfl_xor_sync(0xffffffffu, s, o);
    __shared__ float sm[32];
    if ((tid & 31) == 0) sm[tid >> 5] = s;
    __syncthreads();
    if (tid == 0) {
        float t = 0.f;
        #pragma unroll
        for (int i = 0; i < 32; i++) t += sm[i];
        *out = 0.01f * t * (1.f / (float)M_ROWS);
    }
}

// ---------------------------------------------------------------------------
// Launch
// ---------------------------------------------------------------------------
extern "C" void kernel_launch(void* const* d_in, const int* in_sizes, int n_in,
                              void* d_out, int out_size)
{
    const float* x      = (const float*)d_in[0];
    const float* in_w   = (const float*)d_in[1];
    const float* in_b   = (const float*)d_in[2];
    const float* ln_g   = (const float*)d_in[3];
    const float* ln_b   = (const float*)d_in[4];
    const float* blk_ng = (const float*)d_in[5];
    const float* blk_nb = (const float*)d_in[6];
    const float* blk_ipw= (const float*)d_in[7];
    const float* blk_cw = (const float*)d_in[8];
    const float* blk_cb = (const float*)d_in[9];
    const float* blk_xpw= (const float*)d_in[10];
    const float* blk_dtw= (const float*)d_in[11];
    const float* blk_dtb= (const float*)d_in[12];
    const float* blk_Al = (const float*)d_in[13];
    const float* blk_D  = (const float*)d_in[14];
    const float* blk_opw= (const float*)d_in[15];
    const float* op_w   = (const float*)d_in[16];
    const float* op_b   = (const float*)d_in[17];
    const float* cls_w  = (const float*)d_in[18];
    const float* cls_b  = (const float*)d_in[19];
    float* out = (float*)d_out;

    float *hs, *xz, *u, *ut, *dltt, *yt, *xdbc, *nrm, *part;
    __nv_bfloat16 *lthi, *ltlo, *yhi, *ylo, *hshi, *hslo, *h2hi, *h2lo;
    __nv_bfloat16 *wihi, *wilo, *wphi, *wplo, *wohi, *wolo, *wqhi, *wqlo, *wchi, *wclo;
    cudaGetSymbolAddress((void**)&hs,   g_hl);
    cudaGetSymbolAddress((void**)&xz,   g_xz);
    cudaGetSymbolAddress((void**)&u,    g_u);
    cudaGetSymbolAddress((void**)&ut,   g_ut);
    cudaGetSymbolAddress((void**)&dltt, g_dltt);
    cudaGetSymbolAddress((void**)&yt,   g_yt);
    cudaGetSymbolAddress((void**)&xdbc, g_xdbc);
    cudaGetSymbolAddress((void**)&nrm,  g_norm);
    cudaGetSymbolAddress((void**)&part, g_part);
    cudaGetSymbolAddress((void**)&lthi, g_lthi); cudaGetSymbolAddress((void**)&ltlo, g_ltlo);
    cudaGetSymbolAddress((void**)&yhi,  g_yhi);  cudaGetSymbolAddress((void**)&ylo,  g_ylo);
    cudaGetSymbolAddress((void**)&hshi, g_hshi); cudaGetSymbolAddress((void**)&hslo, g_hslo);
    cudaGetSymbolAddress((void**)&h2hi, g_h2hi); cudaGetSymbolAddress((void**)&h2lo, g_h2lo);
    cudaGetSymbolAddress((void**)&wihi, g_wihi); cudaGetSymbolAddress((void**)&wilo, g_wilo);
    cudaGetSymbolAddress((void**)&wphi, g_wphi); cudaGetSymbolAddress((void**)&wplo, g_wplo);
    cudaGetSymbolAddress((void**)&wohi, g_wohi); cudaGetSymbolAddress((void**)&wolo, g_wolo);
    cudaGetSymbolAddress((void**)&wqhi, g_wqhi); cudaGetSymbolAddress((void**)&wqlo, g_wqlo);
    cudaGetSymbolAddress((void**)&wchi, g_wchi); cudaGetSymbolAddress((void**)&wclo, g_wclo);

    cudaFuncSetAttribute(mma_gemm<1,0>, cudaFuncAttributeMaxDynamicSharedMemorySize, MM_SMEM);
    cudaFuncSetAttribute(mma_gemm<2,0>, cudaFuncAttributeMaxDynamicSharedMemorySize, MM_SMEM);
    cudaFuncSetAttribute(mma_gemm<3,1>, cudaFuncAttributeMaxDynamicSharedMemorySize, MM_SMEM);
    cudaFuncSetAttribute(mma_gemm<4,0>, cudaFuncAttributeMaxDynamicSharedMemorySize, MM_SMEM);

    dim3 blk256(256);
    dim3 tblk(32, 8);
    dim3 tgrid(SEQ / 32, D_INNER / 32, BATCH);
    const int EP_BLOCKS = M_ROWS * 32 / 256;

    cvt_all<<<1056, blk256>>>(in_w, blk_ipw, blk_opw, op_w, cls_w,
                              wihi, wilo, wphi, wplo,
                              wohi, wolo, wqhi, wqlo, wchi, wclo);

    mma_gemm<3,1><<<dim3(D_MODEL / 128, M_ROWS / 128, 3), blk256, MM_SMEM>>>(
        (const __nv_bfloat16*)x, nullptr, wihi, wilo, part, M_ROWS, D_MODEL, X_DIM);
    ep_inproj<3><<<EP_BLOCKS, blk256>>>(part, in_b, ln_g, ln_b,
                                        blk_ng, blk_nb, hs, lthi, ltlo);

    for (int l = 0; l < N_LAYERS; l++) {
        const __nv_bfloat16* pwh = wphi + (size_t)l * 2 * D_INNER * D_MODEL;
        const __nv_bfloat16* pwl = wplo + (size_t)l * 2 * D_INNER * D_MODEL;
        const __nv_bfloat16* owh = wohi + (size_t)l * D_MODEL * D_INNER;
        const __nv_bfloat16* owl = wolo + (size_t)l * D_MODEL * D_INNER;
        const float* cw  = blk_cw  + (size_t)l * D_INNER * D_CONV;
        const float* cb  = blk_cb  + (size_t)l * D_INNER;
        const float* xpw = blk_xpw + (size_t)l * 48 * D_INNER;
        const float* dtw = blk_dtw + (size_t)l * D_INNER * DT_RANK;
        const float* dtb = blk_dtb + (size_t)l * D_INNER;
        const float* Al  = blk_Al  + (size_t)l * D_INNER * D_STATE;
        const float* Dp  = blk_D   + (size_t)l * D_INNER;

        mma_gemm<1,0><<<dim3(2 * D_INNER / 128, M_ROWS / 128, 1), blk256, MM_SMEM>>>(
            lthi, ltlo, pwh, pwl, xz, M_ROWS, 2 * D_INNER, D_MODEL);
        conv2_kernel<<<tgrid, tblk>>>(xz, cw, cb, u, ut);
        gemm_xpw<<<dim3(1, M_ROWS / 128, 4), blk256>>>(
            u, xpw, part, M_ROWS, 48, D_INNER, 4);
        reduce_k<4,0><<<(M_ROWS * 48 / 4 + 255) / 256, blk256>>>(
            part, nullptr, xdbc, M_ROWS * 48, 48);
        deltaT_kernel<<<tgrid, tblk>>>(xdbc, dtw, dtb, dltt);
        scan_fused<<<NGROUP, blk256>>>(dltt, ut, xdbc, Al, Dp, yt);
        gate_kernel<<<tgrid, tblk>>>(yt, xz, yhi, ylo);
        mma_gemm<4,0><<<dim3(D_MODEL / 128, M_ROWS / 128, 4), blk256, MM_SMEM>>>(
            yhi, ylo, owh, owl, part, M_ROWS, D_MODEL, D_INNER);
        if (l + 1 < N_LAYERS) {
            ep_opw<4,1><<<EP_BLOCKS, blk256>>>(part,
                blk_ng + (size_t)(l + 1) * D_MODEL,
                blk_nb + (size_t)(l + 1) * D_MODEL, hs, lthi, ltlo);
        } else {
            ep_opw<4,0><<<EP_BLOCKS, blk256>>>(part, nullptr, nullptr, hs, hshi, hslo);
        }
    }

    mma_gemm<4,0><<<dim3(D_MODEL / 128, M_ROWS / 128, 4), blk256, MM_SMEM>>>(
        hshi, hslo, wqhi, wqlo, part, M_ROWS, D_MODEL, D_MODEL);
    ep_head<4><<<EP_BLOCKS, blk256>>>(part, op_b, h2hi, h2lo, nrm);
    mma_gemm<4,0><<<dim3(N_CLS / 128, M_ROWS / 128, 4), blk256, MM_SMEM>>>(
        h2hi, h2lo, wchi, wclo, part, M_ROWS, N_CLS, D_MODEL);
    reduce_k<4,1><<<(M_ROWS * N_CLS / 4 + 255) / 256, blk256>>>(
        part, cls_b, out, M_ROWS * N_CLS, N_CLS);
    loss_kernel<<<1, 1024>>>(nrm, out + (out_size - 1));
}